// round 5
// baseline (speedup 1.0000x reference)
#include <cuda_runtime.h>
#include <cuda_bf16.h>
#include <cstdint>

typedef unsigned int u32;

#define MAXN 50176   // N=50000 padded to 128
#define MAXE 800000

// ---------------------------------------------------------------------------
// Device-global scratch (no allocation allowed)
// ---------------------------------------------------------------------------
__device__ float g_h[MAXN * 128];
__device__ float g_aggr[MAXN * 128];
__device__ float g_t[MAXN * 256];
__device__ float g_embc[18 * 128];   // emb1[t]+emb2[d]; idx 12 = self-loop
__device__ __nv_bfloat16 g_Wh[81920];  // Wenc@0, W1@16384, W2@49152
__device__ __nv_bfloat16 g_Wl[81920];
// CSR-by-dst edge binning
__device__ int g_cnt[MAXN + 1];
__device__ int g_off[MAXN + 1];
__device__ int g_pos[MAXN + 1];
__device__ u32 g_srt[MAXE];          // packed record: src | (combo<<16)

// ---------------------------------------------------------------------------
// Helpers
// ---------------------------------------------------------------------------
__device__ __forceinline__ u32 smem_u32(const void* p) {
    u32 a;
    asm("{ .reg .u64 t; cvta.to.shared.u64 t, %1; cvt.u32.u64 %0, t; }"
        : "=r"(a) : "l"(p));
    return a;
}

__device__ __forceinline__ void ldsm4(u32& r0, u32& r1, u32& r2, u32& r3, u32 addr) {
    asm volatile("ldmatrix.sync.aligned.m8n8.x4.shared.b16 {%0,%1,%2,%3}, [%4];"
                 : "=r"(r0), "=r"(r1), "=r"(r2), "=r"(r3) : "r"(addr));
}

__device__ __forceinline__ void mma16816(float* c, const u32* a, u32 b0, u32 b1) {
    asm volatile(
        "mma.sync.aligned.m16n8k16.row.col.f32.bf16.bf16.f32 "
        "{%0,%1,%2,%3}, {%4,%5,%6,%7}, {%8,%9}, {%0,%1,%2,%3};"
        : "+f"(c[0]), "+f"(c[1]), "+f"(c[2]), "+f"(c[3])
        : "r"(a[0]), "r"(a[1]), "r"(a[2]), "r"(a[3]), "r"(b0), "r"(b1));
}

__device__ __forceinline__ u32 pack_bf(__nv_bfloat16 a, __nv_bfloat16 b) {
    return (u32)__bfloat16_as_ushort(a) | ((u32)__bfloat16_as_ushort(b) << 16);
}

__device__ __forceinline__ void split4(float4 v, uint2& hi, uint2& lo) {
    __nv_bfloat16 h0 = __float2bfloat16(v.x), h1 = __float2bfloat16(v.y);
    __nv_bfloat16 h2 = __float2bfloat16(v.z), h3 = __float2bfloat16(v.w);
    __nv_bfloat16 l0 = __float2bfloat16(v.x - __bfloat162float(h0));
    __nv_bfloat16 l1 = __float2bfloat16(v.y - __bfloat162float(h1));
    __nv_bfloat16 l2 = __float2bfloat16(v.z - __bfloat162float(h2));
    __nv_bfloat16 l3 = __float2bfloat16(v.w - __bfloat162float(h3));
    hi = make_uint2(pack_bf(h0, h1), pack_bf(h2, h3));
    lo = make_uint2(pack_bf(l0, l1), pack_bf(l2, l3));
}

// ---------------------------------------------------------------------------
// Setup kernels
// ---------------------------------------------------------------------------
__global__ void setup_emb_kernel(const float* __restrict__ emb1,
                                 const float* __restrict__ emb2) {
    int i = threadIdx.x;  // 128 threads
    #pragma unroll
    for (int t = 0; t < 6; t++)
        #pragma unroll
        for (int d = 0; d < 3; d++)
            g_embc[(t * 3 + d) * 128 + i] = emb1[t * 128 + i] + emb2[d * 128 + i];
}

__global__ void conv_kernel(const float* __restrict__ W, int n4,
                            __nv_bfloat16* __restrict__ dh,
                            __nv_bfloat16* __restrict__ dl) {
    int idx = blockIdx.x * blockDim.x + threadIdx.x;
    if (idx >= n4) return;
    float4 v = reinterpret_cast<const float4*>(W)[idx];
    uint2 hi, lo;
    split4(v, hi, lo);
    reinterpret_cast<uint2*>(dh)[idx] = hi;
    reinterpret_cast<uint2*>(dl)[idx] = lo;
}

// ---------------------------------------------------------------------------
// CSR binning: zero counts -> histogram -> scan -> bin
// ---------------------------------------------------------------------------
__global__ void zero_cnt_kernel(int N) {
    int i = blockIdx.x * blockDim.x + threadIdx.x;
    if (i <= N) g_cnt[i] = 0;
}

__global__ void hist_kernel(const int* __restrict__ ei, int E) {
    int e = blockIdx.x * blockDim.x + threadIdx.x;
    if (e >= E) return;
    atomicAdd(&g_cnt[__ldg(ei + E + e)], 1);
}

// Single-block exclusive scan over g_cnt[0..N) -> g_off/g_pos; g_off[N]=E.
__global__ void __launch_bounds__(1024) scan_kernel(int N, int E) {
    __shared__ int warp_s[32];
    const int VPT = (MAXN + 1023) / 1024;   // 49
    int tid = threadIdx.x;
    int lane = tid & 31, wid = tid >> 5;
    int base = tid * VPT;
    int s = 0;
    #pragma unroll
    for (int i = 0; i < VPT; i++) {
        int idx = base + i;
        if (idx < N) s += g_cnt[idx];
    }
    int v = s;
    #pragma unroll
    for (int o = 1; o < 32; o <<= 1) {
        int t = __shfl_up_sync(0xffffffffu, v, o);
        if (lane >= o) v += t;
    }
    if (lane == 31) warp_s[wid] = v;
    __syncthreads();
    if (wid == 0) {
        int w = warp_s[lane];
        #pragma unroll
        for (int o = 1; o < 32; o <<= 1) {
            int t = __shfl_up_sync(0xffffffffu, w, o);
            if (lane >= o) w += t;
        }
        warp_s[lane] = w;
    }
    __syncthreads();
    int run = (v - s) + (wid > 0 ? warp_s[wid - 1] : 0);
    #pragma unroll
    for (int i = 0; i < VPT; i++) {
        int idx = base + i;
        if (idx < N) {
            g_off[idx] = run;
            g_pos[idx] = run;
            run += g_cnt[idx];
        }
    }
    if (tid == 1023) g_off[N] = E;
}

__global__ void bin_kernel(const int* __restrict__ ei,
                           const int* __restrict__ ea, int E) {
    int e = blockIdx.x * blockDim.x + threadIdx.x;
    if (e >= E) return;
    int src = __ldg(ei + e);
    int dst = __ldg(ei + E + e);
    int a0  = __ldg(ea + 2 * e);
    int a1  = __ldg(ea + 2 * e + 1);
    u32 rec = (u32)src | ((u32)(a0 * 3 + a1) << 16);
    int p = atomicAdd(&g_pos[dst], 1);
    g_srt[p] = rec;
}

// ---------------------------------------------------------------------------
// Pull-gather: one warp per node. aggr[n] = h[n]+selfc + sum(h[src]+embc[cb]).
// No float atomics; register accumulation; one plain 512B store per node.
// ---------------------------------------------------------------------------
__global__ void gather_kernel(int N) {
    int g = blockIdx.x * blockDim.x + threadIdx.x;
    int n = g >> 5;
    int lane = g & 31;
    if (n >= N) return;

    const float4* hb = reinterpret_cast<const float4*>(g_h);
    const float4* eb = reinterpret_cast<const float4*>(g_embc);

    // self-loop: h[n] (post-mask) + selfc
    float4 acc = hb[(size_t)n * 32 + lane];
    float4 sc = eb[12 * 32 + lane];
    acc.x += sc.x; acc.y += sc.y; acc.z += sc.z; acc.w += sc.w;

    int start = g_off[n], end = g_off[n + 1];
    for (int base = start; base < end; base += 32) {
        int rem = end - base;
        int cnt = rem < 32 ? rem : 32;
        u32 my = (lane < cnt) ? g_srt[base + lane] : 0u;
        for (int j = 0; j < cnt; j++) {
            u32 rec = __shfl_sync(0xffffffffu, my, j);
            int src = rec & 0xFFFF;
            int cb  = rec >> 16;
            float4 hv = hb[(size_t)src * 32 + lane];
            float4 ev = eb[cb * 32 + lane];
            acc.x += hv.x + ev.x;
            acc.y += hv.y + ev.y;
            acc.z += hv.z + ev.z;
            acc.w += hv.w + ev.w;
        }
    }
    reinterpret_cast<float4*>(g_aggr)[(size_t)n * 32 + lane] = acc;
}

// ---------------------------------------------------------------------------
// HMMA bf16 split GEMM: C[M,Ntot] = f(A[M,K] @ B[Ntot,K]^T + bias)
// CTA 128x128, 256 threads (8 warps, 2x4), warp tile 64x32, k16 steps.
// D = Ah@Bh + Ah@Bl + Al@Bh (fp32 accum in regs).
// ---------------------------------------------------------------------------
template <int KST, bool PRELU, bool RELU, bool BIAS>
__global__ void __launch_bounds__(256)
mma_gemm(const float* __restrict__ A,
         const __nv_bfloat16* __restrict__ Bh, const __nv_bfloat16* __restrict__ Bl,
         const float* __restrict__ bias, const float* __restrict__ prelu_pa,
         float* __restrict__ C, int M, int Ntot) {
    constexpr int RS = 272;               // smem row stride bytes (128 bf16 + 8 pad)
    constexpr int BUF = 128 * RS;
    extern __shared__ __align__(16) char smem[];
    char* sAh = smem;
    char* sAl = smem + BUF;
    char* sBh = smem + 2 * BUF;
    char* sBl = smem + 3 * BUF;

    const int tid = threadIdx.x;
    const int wid = tid >> 5, lid = tid & 31;
    const int wm = wid >> 2;
    const int wn = wid & 3;
    const int rowbase = blockIdx.x * 128;
    const int colbase = blockIdx.y * 128;
    const int K = KST * 128;

    const u32 aAh = smem_u32(sAh), aAl = smem_u32(sAl);
    const u32 aBh = smem_u32(sBh), aBl = smem_u32(sBl);

    float pa = PRELU ? *prelu_pa : 0.f;

    float acc[4][4][4];
    #pragma unroll
    for (int i = 0; i < 4; i++)
        #pragma unroll
        for (int j = 0; j < 4; j++)
            #pragma unroll
            for (int q = 0; q < 4; q++) acc[i][j][q] = 0.f;

    for (int s = 0; s < KST; s++) {
        if (s > 0) __syncthreads();

        #pragma unroll
        for (int i = 0; i < 16; i++) {
            int idx = i * 256 + tid;
            int row = idx >> 5;
            int c4 = idx & 31;
            int grow = rowbase + row;
            float4 v = make_float4(0.f, 0.f, 0.f, 0.f);
            if (grow < M)
                v = *reinterpret_cast<const float4*>(A + (size_t)grow * K + s * 128 + c4 * 4);
            if (PRELU) {
                v.x = v.x > 0.f ? v.x : pa * v.x;
                v.y = v.y > 0.f ? v.y : pa * v.y;
                v.z = v.z > 0.f ? v.z : pa * v.z;
                v.w = v.w > 0.f ? v.w : pa * v.w;
            }
            uint2 hi, lo;
            split4(v, hi, lo);
            *reinterpret_cast<uint2*>(sAh + row * RS + c4 * 8) = hi;
            *reinterpret_cast<uint2*>(sAl + row * RS + c4 * 8) = lo;
        }

        #pragma unroll
        for (int i = 0; i < 16; i++) {
            int idx = i * 256 + tid;
            int row = idx >> 5;
            int j = idx & 31;
            const __nv_bfloat16* srh = Bh + (size_t)(colbase + row) * K + s * 128;
            const __nv_bfloat16* srl = Bl + (size_t)(colbase + row) * K + s * 128;
            *reinterpret_cast<uint2*>(sBh + row * RS + j * 8) =
                reinterpret_cast<const uint2*>(srh)[j];
            *reinterpret_cast<uint2*>(sBl + row * RS + j * 8) =
                reinterpret_cast<const uint2*>(srl)[j];
        }

        __syncthreads();

        #pragma unroll
        for (int k = 0; k < 8; k++) {
            u32 bh[2][4], bl[2][4];
            #pragma unroll
            for (int nj = 0; nj < 2; nj++) {
                int row = wn * 32 + nj * 16 + (lid & 7) + ((lid >> 4) << 3);
                int colb = k * 32 + ((lid >> 3) & 1) * 16;
                ldsm4(bh[nj][0], bh[nj][1], bh[nj][2], bh[nj][3], aBh + row * RS + colb);
                ldsm4(bl[nj][0], bl[nj][1], bl[nj][2], bl[nj][3], aBl + row * RS + colb);
            }
            #pragma unroll
            for (int mi = 0; mi < 4; mi++) {
                int arow = wm * 64 + mi * 16 + (lid & 15);
                int acolb = k * 32 + ((lid >> 4) << 4);
                u32 ah[4], al[4];
                ldsm4(ah[0], ah[1], ah[2], ah[3], aAh + arow * RS + acolb);
                ldsm4(al[0], al[1], al[2], al[3], aAl + arow * RS + acolb);
                #pragma unroll
                for (int n8 = 0; n8 < 4; n8++) {
                    int nj = n8 >> 1, p = (n8 & 1) * 2;
                    mma16816(acc[mi][n8], ah, bh[nj][p], bh[nj][p + 1]);
                    mma16816(acc[mi][n8], ah, bl[nj][p], bl[nj][p + 1]);
                    mma16816(acc[mi][n8], al, bh[nj][p], bh[nj][p + 1]);
                }
            }
        }
    }

    // ---- epilogue ----
    const int g = lid >> 2, t = lid & 3;
    #pragma unroll
    for (int mi = 0; mi < 4; mi++) {
        #pragma unroll
        for (int n8 = 0; n8 < 4; n8++) {
            int gr0 = rowbase + wm * 64 + mi * 16 + g;
            int gr1 = gr0 + 8;
            int gc  = colbase + wn * 32 + n8 * 8 + 2 * t;
            float c0 = acc[mi][n8][0], c1 = acc[mi][n8][1];
            float c2 = acc[mi][n8][2], c3 = acc[mi][n8][3];
            if (BIAS) {
                float bb0 = __ldg(bias + gc), bb1 = __ldg(bias + gc + 1);
                c0 += bb0; c1 += bb1; c2 += bb0; c3 += bb1;
            }
            if (RELU) {
                c0 = fmaxf(c0, 0.f); c1 = fmaxf(c1, 0.f);
                c2 = fmaxf(c2, 0.f); c3 = fmaxf(c3, 0.f);
            }
            if (gr0 < M)
                *reinterpret_cast<float2*>(C + (size_t)gr0 * Ntot + gc) = make_float2(c0, c1);
            if (gr1 < M)
                *reinterpret_cast<float2*>(C + (size_t)gr1 * Ntot + gc) = make_float2(c2, c3);
        }
    }
}

// ---------------------------------------------------------------------------
// Mask: h[m] = 0 (aggr handled entirely by gather)
// ---------------------------------------------------------------------------
__global__ void mask_kernel(const int* __restrict__ mask, int Mm) {
    int g = blockIdx.x * blockDim.x + threadIdx.x;
    int i = g >> 5;
    int lane = g & 31;
    if (i >= Mm) return;
    int row = __ldg(mask + i);
    *reinterpret_cast<float4*>(g_h + (size_t)row * 128 + lane * 4) =
        make_float4(0.f, 0.f, 0.f, 0.f);
}

// ---------------------------------------------------------------------------
// Host launch
// ---------------------------------------------------------------------------
extern "C" void kernel_launch(void* const* d_in, const int* in_sizes, int n_in,
                              void* d_out, int out_size) {
    const float* x    = (const float*)d_in[0];
    const int*   ei   = (const int*)d_in[1];
    const int*   ea   = (const int*)d_in[2];
    const int*   mask = (const int*)d_in[3];
    const float* pa   = (const float*)d_in[4];
    const float* Wenc = (const float*)d_in[5];
    const float* W1   = (const float*)d_in[6];
    const float* b1   = (const float*)d_in[7];
    const float* W2   = (const float*)d_in[8];
    const float* b2   = (const float*)d_in[9];
    const float* emb1 = (const float*)d_in[10];
    const float* emb2 = (const float*)d_in[11];

    int N  = in_sizes[0] / 128;
    int E  = in_sizes[1] / 2;
    int Mm = in_sizes[3];
    float* out = (float*)d_out;

    float *h, *aggr, *t;
    __nv_bfloat16 *wh, *wl;
    cudaGetSymbolAddress((void**)&h,    g_h);
    cudaGetSymbolAddress((void**)&aggr, g_aggr);
    cudaGetSymbolAddress((void**)&t,    g_t);
    cudaGetSymbolAddress((void**)&wh,   g_Wh);
    cudaGetSymbolAddress((void**)&wl,   g_Wl);

    constexpr int SMEMSZ = 4 * 128 * 272;   // 139264 B
    cudaFuncSetAttribute(mma_gemm<1, true,  false, false>,
                         cudaFuncAttributeMaxDynamicSharedMemorySize, SMEMSZ);
    cudaFuncSetAttribute(mma_gemm<1, false, true,  true>,
                         cudaFuncAttributeMaxDynamicSharedMemorySize, SMEMSZ);
    cudaFuncSetAttribute(mma_gemm<2, false, false, true>,
                         cudaFuncAttributeMaxDynamicSharedMemorySize, SMEMSZ);

    // 0) setup: embedding combos + weight splits (input-only)
    setup_emb_kernel<<<1, 128>>>(emb1, emb2);
    conv_kernel<<<16, 256>>>(Wenc, 4096, wh,          wl);
    conv_kernel<<<32, 256>>>(W1,   8192, wh + 16384,  wl + 16384);
    conv_kernel<<<32, 256>>>(W2,   8192, wh + 49152,  wl + 49152);

    // 1) CSR binning of edges by dst (input-only; independent of h)
    zero_cnt_kernel<<<(N + 256) / 256, 256>>>(N);
    hist_kernel<<<(E + 255) / 256, 256>>>(ei, E);
    scan_kernel<<<1, 1024>>>(N, E);
    bin_kernel<<<(E + 255) / 256, 256>>>(ei, ea, E);

    int gx = (N + 127) / 128;

    // 2) G1: h = PReLU(x) @ Wenc^T
    mma_gemm<1, true, false, false><<<dim3(gx, 1), 256, SMEMSZ>>>(
        x, wh, wl, nullptr, pa, h, N, 128);

    // 3) mask: h[m]=0
    mask_kernel<<<(Mm * 32 + 255) / 256, 256>>>(mask, Mm);

    // 4) pull-gather: aggr = h + selfc + sum of messages (no atomics)
    gather_kernel<<<(N * 32 + 255) / 256, 256>>>(N);

    // 5) G2: t = relu(aggr @ W1^T + b1)
    mma_gemm<1, false, true, true><<<dim3(gx, 2), 256, SMEMSZ>>>(
        aggr, wh + 16384, wl + 16384, b1, nullptr, t, N, 256);

    // 6) G3: out = t @ W2^T + b2
    mma_gemm<2, false, false, true><<<dim3(gx, 1), 256, SMEMSZ>>>(
        t, wh + 49152, wl + 49152, b2, nullptr, out, N, 128);
}

// round 6
// speedup vs baseline: 1.2045x; 1.2045x over previous
#include <cuda_runtime.h>
#include <cuda_bf16.h>
#include <cstdint>

typedef unsigned int u32;

#define MAXN 50176   // N=50000 padded to 128

// ---------------------------------------------------------------------------
// Device-global scratch (no allocation allowed)
// ---------------------------------------------------------------------------
__device__ float g_h[MAXN * 128];
__device__ float g_aggr[MAXN * 128];
__device__ float g_embc[18 * 128];      // emb1[t]+emb2[d]; idx 12 = self-loop
__device__ __nv_bfloat16 g_Wh[81920];   // Wenc@0, W1@16384, W2@49152 ([out][K])
__device__ __nv_bfloat16 g_Wl[81920];
__device__ __nv_bfloat16 g_th[MAXN * 256];  // t split hi
__device__ __nv_bfloat16 g_tl[MAXN * 256];  // t split lo

// ---------------------------------------------------------------------------
// Helpers
// ---------------------------------------------------------------------------
__device__ __forceinline__ u32 smem_u32(const void* p) {
    u32 a;
    asm("{ .reg .u64 t; cvta.to.shared.u64 t, %1; cvt.u32.u64 %0, t; }"
        : "=r"(a) : "l"(p));
    return a;
}
__device__ __forceinline__ void cpa16(u32 dst, const void* src) {
    asm volatile("cp.async.cg.shared.global [%0], [%1], 16;" :: "r"(dst), "l"(src));
}
__device__ __forceinline__ void cpa_commit() {
    asm volatile("cp.async.commit_group;" ::: "memory");
}
__device__ __forceinline__ void cpa_wait0() {
    asm volatile("cp.async.wait_group 0;" ::: "memory");
}
__device__ __forceinline__ void ldsm4(u32& r0, u32& r1, u32& r2, u32& r3, u32 addr) {
    asm volatile("ldmatrix.sync.aligned.m8n8.x4.shared.b16 {%0,%1,%2,%3}, [%4];"
                 : "=r"(r0), "=r"(r1), "=r"(r2), "=r"(r3) : "r"(addr));
}
__device__ __forceinline__ void mma16816(float* c, const u32* a, u32 b0, u32 b1) {
    asm volatile(
        "mma.sync.aligned.m16n8k16.row.col.f32.bf16.bf16.f32 "
        "{%0,%1,%2,%3}, {%4,%5,%6,%7}, {%8,%9}, {%0,%1,%2,%3};"
        : "+f"(c[0]), "+f"(c[1]), "+f"(c[2]), "+f"(c[3])
        : "r"(a[0]), "r"(a[1]), "r"(a[2]), "r"(a[3]), "r"(b0), "r"(b1));
}
__device__ __forceinline__ u32 pack_bf(__nv_bfloat16 a, __nv_bfloat16 b) {
    return (u32)__bfloat16_as_ushort(a) | ((u32)__bfloat16_as_ushort(b) << 16);
}
__device__ __forceinline__ void split4(float4 v, uint2& hi, uint2& lo) {
    __nv_bfloat16 h0 = __float2bfloat16(v.x), h1 = __float2bfloat16(v.y);
    __nv_bfloat16 h2 = __float2bfloat16(v.z), h3 = __float2bfloat16(v.w);
    __nv_bfloat16 l0 = __float2bfloat16(v.x - __bfloat162float(h0));
    __nv_bfloat16 l1 = __float2bfloat16(v.y - __bfloat162float(h1));
    __nv_bfloat16 l2 = __float2bfloat16(v.z - __bfloat162float(h2));
    __nv_bfloat16 l3 = __float2bfloat16(v.w - __bfloat162float(h3));
    hi = make_uint2(pack_bf(h0, h1), pack_bf(h2, h3));
    lo = make_uint2(pack_bf(l0, l1), pack_bf(l2, l3));
}

// ---------------------------------------------------------------------------
// Setup kernels
// ---------------------------------------------------------------------------
__global__ void setup_emb_kernel(const float* __restrict__ emb1,
                                 const float* __restrict__ emb2) {
    int i = threadIdx.x;  // 128 threads
    #pragma unroll
    for (int t = 0; t < 6; t++)
        #pragma unroll
        for (int d = 0; d < 3; d++)
            g_embc[(t * 3 + d) * 128 + i] = emb1[t * 128 + i] + emb2[d * 128 + i];
}

// Split all 3 weight matrices -> bf16 hi/lo in one launch.
__global__ void conv_all_kernel(const float* __restrict__ Wenc,
                                const float* __restrict__ W1,
                                const float* __restrict__ W2) {
    int idx = blockIdx.x * blockDim.x + threadIdx.x;   // 0..20479 float4 slots
    const float* src;
    int off;
    if (idx < 4096)       { src = Wenc; off = 0;     idx -= 0; }
    else if (idx < 12288) { src = W1;   off = 4096;  idx -= 4096; }
    else if (idx < 20480) { src = W2;   off = 12288; idx -= 12288; }
    else return;
    float4 v = reinterpret_cast<const float4*>(src)[idx];
    uint2 hi, lo;
    split4(v, hi, lo);
    reinterpret_cast<uint2*>(g_Wh)[off + idx] = hi;
    reinterpret_cast<uint2*>(g_Wl)[off + idx] = lo;
}

// ---------------------------------------------------------------------------
// Double-buffered HMMA bf16 split GEMM.
// C[M,Ntot] = f(A[M,K] @ B[Ntot,K]^T + bias),  D = Ah@Bh + Ah@Bl + Al@Bh.
// CTA 128x128, 256 thr (8 warps 2x4), K chunks of 64, 2-stage smem pipeline.
// ASPLIT: A fp32 (LDG+split+STS) else A pre-split bf16 (cp.async).
// WRITEC: store fp32 C (+DUAL C2=C+addvec). TOUT: store split bf16 Th/Tl.
// ---------------------------------------------------------------------------
constexpr int RS   = 144;                 // smem row stride bytes (64 bf16 + 8 pad)
constexpr int TB   = 128 * RS;            // 18432 per tile buffer
constexpr int OAH = 0, OAL = TB, OBH = 2 * TB, OBL = 3 * TB;
constexpr int STG  = 4 * TB;              // 73728 per stage
constexpr int SMEMSZ = 2 * STG;           // 147456

template <int NC, bool ASPLIT, bool PRELU, bool RELU, bool BIAS, bool DUAL,
          bool WRITEC, bool TOUT>
__global__ void __launch_bounds__(256)
mma_gemm(const float* __restrict__ A,
         const __nv_bfloat16* __restrict__ Asph, const __nv_bfloat16* __restrict__ Aspl,
         const __nv_bfloat16* __restrict__ Bh, const __nv_bfloat16* __restrict__ Bl,
         const float* __restrict__ bias, const float* __restrict__ prelu_pa,
         float* __restrict__ C, float* __restrict__ C2,
         const float* __restrict__ addvec,
         __nv_bfloat16* __restrict__ Th, __nv_bfloat16* __restrict__ Tl,
         int M, int Ntot) {
    extern __shared__ __align__(16) char smem[];
    const u32 s0 = smem_u32(smem);

    const int tid = threadIdx.x;
    const int wid = tid >> 5, lid = tid & 31;
    const int wm = wid >> 2;              // 0..1
    const int wn = wid & 3;               // 0..3
    const int rowbase = blockIdx.x * 128;
    const int colbase = blockIdx.y * 128;
    const int K = NC * 64;

    const float pa = PRELU ? *prelu_pa : 0.f;

    float acc[4][4][4];
    #pragma unroll
    for (int i = 0; i < 4; i++)
        #pragma unroll
        for (int j = 0; j < 4; j++)
            #pragma unroll
            for (int q = 0; q < 4; q++) acc[i][j][q] = 0.f;

    float4 av[4][2];

    // ---- helpers (inlined lambdas) ----
    auto ldgA = [&](int c) {
        #pragma unroll
        for (int i = 0; i < 4; i++) {
            int p = i * 256 + tid;
            int row = p >> 3, cp = p & 7;
            int grow = rowbase + row;
            if (grow < M) {
                const float4* s = reinterpret_cast<const float4*>(
                    A + (size_t)grow * K + c * 64 + cp * 8);
                av[i][0] = s[0]; av[i][1] = s[1];
            } else {
                av[i][0] = make_float4(0.f, 0.f, 0.f, 0.f);
                av[i][1] = make_float4(0.f, 0.f, 0.f, 0.f);
            }
        }
    };
    auto splitSTS = [&](u32 sb) {
        #pragma unroll
        for (int i = 0; i < 4; i++) {
            int p = i * 256 + tid;
            int row = p >> 3, cp = p & 7;
            float4 v0 = av[i][0], v1 = av[i][1];
            if (PRELU) {
                v0.x = v0.x > 0.f ? v0.x : pa * v0.x;
                v0.y = v0.y > 0.f ? v0.y : pa * v0.y;
                v0.z = v0.z > 0.f ? v0.z : pa * v0.z;
                v0.w = v0.w > 0.f ? v0.w : pa * v0.w;
                v1.x = v1.x > 0.f ? v1.x : pa * v1.x;
                v1.y = v1.y > 0.f ? v1.y : pa * v1.y;
                v1.z = v1.z > 0.f ? v1.z : pa * v1.z;
                v1.w = v1.w > 0.f ? v1.w : pa * v1.w;
            }
            uint2 h0, l0, h1, l1;
            split4(v0, h0, l0);
            split4(v1, h1, l1);
            *reinterpret_cast<uint4*>(smem + (sb - s0) + OAH + row * RS + cp * 16) =
                make_uint4(h0.x, h0.y, h1.x, h1.y);
            *reinterpret_cast<uint4*>(smem + (sb - s0) + OAL + row * RS + cp * 16) =
                make_uint4(l0.x, l0.y, l1.x, l1.y);
        }
    };
    auto cpB = [&](int c, u32 sb) {
        #pragma unroll
        for (int i = 0; i < 4; i++) {
            int j = i * 256 + tid;
            int row = j >> 3, c16 = j & 7;
            size_t go = (size_t)(colbase + row) * K + c * 64 + c16 * 8;
            cpa16(sb + OBH + row * RS + c16 * 16, Bh + go);
            cpa16(sb + OBL + row * RS + c16 * 16, Bl + go);
        }
    };
    auto cpA = [&](int c, u32 sb) {
        #pragma unroll
        for (int i = 0; i < 4; i++) {
            int j = i * 256 + tid;
            int row = j >> 3, c16 = j & 7;
            size_t go = (size_t)(rowbase + row) * K + c * 64 + c16 * 8;
            cpa16(sb + OAH + row * RS + c16 * 16, Asph + go);
            cpa16(sb + OAL + row * RS + c16 * 16, Aspl + go);
        }
    };
    auto compute = [&](u32 sb) {
        #pragma unroll
        for (int k = 0; k < 4; k++) {
            u32 bh[2][4], bl[2][4];
            #pragma unroll
            for (int nj = 0; nj < 2; nj++) {
                int row = wn * 32 + nj * 16 + (lid & 7) + ((lid >> 4) << 3);
                int colb = k * 32 + ((lid >> 3) & 1) * 16;
                ldsm4(bh[nj][0], bh[nj][1], bh[nj][2], bh[nj][3],
                      sb + OBH + row * RS + colb);
                ldsm4(bl[nj][0], bl[nj][1], bl[nj][2], bl[nj][3],
                      sb + OBL + row * RS + colb);
            }
            #pragma unroll
            for (int mi = 0; mi < 4; mi++) {
                int arow = wm * 64 + mi * 16 + (lid & 15);
                int acolb = k * 32 + ((lid >> 4) << 4);
                u32 ah[4], al[4];
                ldsm4(ah[0], ah[1], ah[2], ah[3], sb + OAH + arow * RS + acolb);
                ldsm4(al[0], al[1], al[2], al[3], sb + OAL + arow * RS + acolb);
                #pragma unroll
                for (int n8 = 0; n8 < 4; n8++) {
                    int nj = n8 >> 1, p = (n8 & 1) * 2;
                    mma16816(acc[mi][n8], ah, bh[nj][p], bh[nj][p + 1]);
                    mma16816(acc[mi][n8], ah, bl[nj][p], bl[nj][p + 1]);
                    mma16816(acc[mi][n8], al, bh[nj][p], bh[nj][p + 1]);
                }
            }
        }
    };

    // ---- prologue: chunk 0 into stage 0 ----
    if (ASPLIT) ldgA(0); else cpA(0, s0);
    cpB(0, s0);
    cpa_commit();
    if (ASPLIT) splitSTS(s0);
    cpa_wait0();
    __syncthreads();

    // ---- pipelined mainloop ----
    #pragma unroll
    for (int c = 0; c < NC; c++) {
        u32 sb = s0 + (c & 1) * STG;
        u32 sn = s0 + ((c + 1) & 1) * STG;
        if (c + 1 < NC) {
            if (ASPLIT) ldgA(c + 1); else cpA(c + 1, sn);
            cpB(c + 1, sn);
            cpa_commit();
        }
        compute(sb);
        if (c + 1 < NC) {
            if (ASPLIT) splitSTS(sn);
            cpa_wait0();
            __syncthreads();
        }
    }

    // ---- epilogue ----
    const int g = lid >> 2, t = lid & 3;
    #pragma unroll
    for (int mi = 0; mi < 4; mi++) {
        #pragma unroll
        for (int n8 = 0; n8 < 4; n8++) {
            int gr0 = rowbase + wm * 64 + mi * 16 + g;
            int gr1 = gr0 + 8;
            int gc  = colbase + wn * 32 + n8 * 8 + 2 * t;
            float c0 = acc[mi][n8][0], c1 = acc[mi][n8][1];
            float c2 = acc[mi][n8][2], c3 = acc[mi][n8][3];
            if (BIAS) {
                float bb0 = __ldg(bias + gc), bb1 = __ldg(bias + gc + 1);
                c0 += bb0; c1 += bb1; c2 += bb0; c3 += bb1;
            }
            if (RELU) {
                c0 = fmaxf(c0, 0.f); c1 = fmaxf(c1, 0.f);
                c2 = fmaxf(c2, 0.f); c3 = fmaxf(c3, 0.f);
            }
            if (WRITEC) {
                float av0 = 0.f, av1 = 0.f;
                if (DUAL) { av0 = __ldg(addvec + gc); av1 = __ldg(addvec + gc + 1); }
                if (gr0 < M) {
                    *reinterpret_cast<float2*>(C + (size_t)gr0 * Ntot + gc) =
                        make_float2(c0, c1);
                    if (DUAL)
                        *reinterpret_cast<float2*>(C2 + (size_t)gr0 * Ntot + gc) =
                            make_float2(c0 + av0, c1 + av1);
                }
                if (gr1 < M) {
                    *reinterpret_cast<float2*>(C + (size_t)gr1 * Ntot + gc) =
                        make_float2(c2, c3);
                    if (DUAL)
                        *reinterpret_cast<float2*>(C2 + (size_t)gr1 * Ntot + gc) =
                            make_float2(c2 + av0, c3 + av1);
                }
            }
            if (TOUT) {
                if (gr0 < M) {
                    __nv_bfloat16 h0 = __float2bfloat16(c0), h1 = __float2bfloat16(c1);
                    __nv_bfloat16 l0 = __float2bfloat16(c0 - __bfloat162float(h0));
                    __nv_bfloat16 l1 = __float2bfloat16(c1 - __bfloat162float(h1));
                    *reinterpret_cast<u32*>(Th + (size_t)gr0 * Ntot + gc) = pack_bf(h0, h1);
                    *reinterpret_cast<u32*>(Tl + (size_t)gr0 * Ntot + gc) = pack_bf(l0, l1);
                }
                if (gr1 < M) {
                    __nv_bfloat16 h2 = __float2bfloat16(c2), h3 = __float2bfloat16(c3);
                    __nv_bfloat16 l2 = __float2bfloat16(c2 - __bfloat162float(h2));
                    __nv_bfloat16 l3 = __float2bfloat16(c3 - __bfloat162float(h3));
                    *reinterpret_cast<u32*>(Th + (size_t)gr1 * Ntot + gc) = pack_bf(h2, h3);
                    *reinterpret_cast<u32*>(Tl + (size_t)gr1 * Ntot + gc) = pack_bf(l2, l3);
                }
            }
        }
    }
}

// ---------------------------------------------------------------------------
// Mask fix: h[m] = 0 ; aggr[m] = selfc (= embc[12])
// ---------------------------------------------------------------------------
__global__ void mask_kernel(const int* __restrict__ mask, int Mm) {
    int g = blockIdx.x * blockDim.x + threadIdx.x;
    int i = g >> 5;
    int lane = g & 31;
    if (i >= Mm) return;
    int row = __ldg(mask + i);
    *reinterpret_cast<float4*>(g_h + (size_t)row * 128 + lane * 4) =
        make_float4(0.f, 0.f, 0.f, 0.f);
    *reinterpret_cast<float4*>(g_aggr + (size_t)row * 128 + lane * 4) =
        *reinterpret_cast<const float4*>(g_embc + 12 * 128 + lane * 4);
}

// ---------------------------------------------------------------------------
// Edge scatter: one warp per edge. aggr[dst] += h[src] + embc[a0*3+a1]
// ---------------------------------------------------------------------------
__global__ void scatter_kernel(const int* __restrict__ ei,
                               const int* __restrict__ ea, int E) {
    int g = blockIdx.x * blockDim.x + threadIdx.x;
    int e = g >> 5;
    int lane = g & 31;
    if (e >= E) return;
    int src = __ldg(ei + e);
    int dst = __ldg(ei + E + e);
    int a0  = __ldg(ea + 2 * e);
    int a1  = __ldg(ea + 2 * e + 1);

    float4 hv = *reinterpret_cast<const float4*>(g_h + (size_t)src * 128 + lane * 4);
    float4 ev = *reinterpret_cast<const float4*>(g_embc + (a0 * 3 + a1) * 128 + lane * 4);
    float4 m = make_float4(hv.x + ev.x, hv.y + ev.y, hv.z + ev.z, hv.w + ev.w);

    float* p = g_aggr + (size_t)dst * 128 + lane * 4;
    asm volatile("red.global.add.v4.f32 [%0], {%1, %2, %3, %4};"
                 :: "l"(p), "f"(m.x), "f"(m.y), "f"(m.z), "f"(m.w)
                 : "memory");
}

// ---------------------------------------------------------------------------
// Host launch
// ---------------------------------------------------------------------------
extern "C" void kernel_launch(void* const* d_in, const int* in_sizes, int n_in,
                              void* d_out, int out_size) {
    const float* x    = (const float*)d_in[0];
    const int*   ei   = (const int*)d_in[1];
    const int*   ea   = (const int*)d_in[2];
    const int*   mask = (const int*)d_in[3];
    const float* pa   = (const float*)d_in[4];
    const float* Wenc = (const float*)d_in[5];
    const float* W1   = (const float*)d_in[6];
    const float* b1   = (const float*)d_in[7];
    const float* W2   = (const float*)d_in[8];
    const float* b2   = (const float*)d_in[9];
    const float* emb1 = (const float*)d_in[10];
    const float* emb2 = (const float*)d_in[11];

    int N  = in_sizes[0] / 128;
    int E  = in_sizes[1] / 2;
    int Mm = in_sizes[3];
    float* out = (float*)d_out;

    float *h, *aggr, *embc;
    __nv_bfloat16 *wh, *wl, *th, *tl;
    cudaGetSymbolAddress((void**)&h,    g_h);
    cudaGetSymbolAddress((void**)&aggr, g_aggr);
    cudaGetSymbolAddress((void**)&embc, g_embc);
    cudaGetSymbolAddress((void**)&wh,   g_Wh);
    cudaGetSymbolAddress((void**)&wl,   g_Wl);
    cudaGetSymbolAddress((void**)&th,   g_th);
    cudaGetSymbolAddress((void**)&tl,   g_tl);

    // G1: fp32-A, PReLU, DUAL aggr init, fp32 out
    auto k1 = mma_gemm<2, true,  true,  false, false, true,  true,  false>;
    // G2: fp32-A, RELU+bias, split-bf16 out only
    auto k2 = mma_gemm<2, true,  false, true,  true,  false, false, true>;
    // G3: bf16-A (cp.async), bias, fp32 out
    auto k3 = mma_gemm<4, false, false, false, true,  false, true,  false>;
    cudaFuncSetAttribute(k1, cudaFuncAttributeMaxDynamicSharedMemorySize, SMEMSZ);
    cudaFuncSetAttribute(k2, cudaFuncAttributeMaxDynamicSharedMemorySize, SMEMSZ);
    cudaFuncSetAttribute(k3, cudaFuncAttributeMaxDynamicSharedMemorySize, SMEMSZ);

    // 0) setup: embedding combos + weight splits
    setup_emb_kernel<<<1, 128>>>(emb1, emb2);
    conv_all_kernel<<<80, 256>>>(Wenc, W1, W2);

    int gx = (N + 127) / 128;

    // 1) G1: h = PReLU(x) @ Wenc^T ; aggr = h + selfc
    k1<<<dim3(gx, 1), 256, SMEMSZ>>>(x, nullptr, nullptr, wh, wl, nullptr, pa,
                                     h, aggr, embc + 12 * 128, nullptr, nullptr,
                                     N, 128);

    // 2) mask: h[m]=0, aggr[m]=selfc
    mask_kernel<<<(Mm * 32 + 255) / 256, 256>>>(mask, Mm);

    // 3) edge scatter (atomic accumulate into aggr)
    long long nthr = (long long)E * 32;
    scatter_kernel<<<(unsigned)((nthr + 255) / 256), 256>>>(ei, ea, E);

    // 4) G2: t = relu(aggr @ W1^T + b1) -> split bf16 th/tl
    k2<<<dim3(gx, 2), 256, SMEMSZ>>>(aggr, nullptr, nullptr, wh + 16384, wl + 16384,
                                     b1, nullptr, nullptr, nullptr, nullptr,
                                     th, tl, N, 256);

    // 5) G3: out = t @ W2^T + b2
    k3<<<dim3(gx, 1), 256, SMEMSZ>>>(nullptr, th, tl, wh + 49152, wl + 49152,
                                     b2, nullptr, out, nullptr, nullptr,
                                     nullptr, nullptr, N, 128);
}

// round 7
// speedup vs baseline: 1.2956x; 1.0756x over previous
#include <cuda_runtime.h>
#include <cuda_bf16.h>
#include <cstdint>

typedef unsigned int u32;

#define MAXN 50176   // N=50000 padded to 128

// ---------------------------------------------------------------------------
// Device-global scratch (no allocation allowed)
// ---------------------------------------------------------------------------
__device__ float g_h[MAXN * 128];
__device__ float g_aggr[MAXN * 128];
__device__ float g_embc[18 * 128];      // emb1[t]+emb2[d]; idx 12 = self-loop
__device__ __nv_bfloat16 g_Wh[81920];   // Wenc@0, W1@16384, W2@49152 ([out][K])
__device__ __nv_bfloat16 g_Wl[81920];
__device__ __nv_bfloat16 g_th[MAXN * 256];  // t split hi
__device__ __nv_bfloat16 g_tl[MAXN * 256];  // t split lo
__device__ unsigned char g_mflag[MAXN];     // 1 = masked node

// ---------------------------------------------------------------------------
// Helpers
// ---------------------------------------------------------------------------
__device__ __forceinline__ u32 smem_u32(const void* p) {
    u32 a;
    asm("{ .reg .u64 t; cvta.to.shared.u64 t, %1; cvt.u32.u64 %0, t; }"
        : "=r"(a) : "l"(p));
    return a;
}
__device__ __forceinline__ void cpa16(u32 dst, const void* src) {
    asm volatile("cp.async.cg.shared.global [%0], [%1], 16;" :: "r"(dst), "l"(src));
}
__device__ __forceinline__ void cpa_commit() {
    asm volatile("cp.async.commit_group;" ::: "memory");
}
__device__ __forceinline__ void cpa_wait0() {
    asm volatile("cp.async.wait_group 0;" ::: "memory");
}
__device__ __forceinline__ void ldsm4(u32& r0, u32& r1, u32& r2, u32& r3, u32 addr) {
    asm volatile("ldmatrix.sync.aligned.m8n8.x4.shared.b16 {%0,%1,%2,%3}, [%4];"
                 : "=r"(r0), "=r"(r1), "=r"(r2), "=r"(r3) : "r"(addr));
}
__device__ __forceinline__ void mma16816(float* c, const u32* a, u32 b0, u32 b1) {
    asm volatile(
        "mma.sync.aligned.m16n8k16.row.col.f32.bf16.bf16.f32 "
        "{%0,%1,%2,%3}, {%4,%5,%6,%7}, {%8,%9}, {%0,%1,%2,%3};"
        : "+f"(c[0]), "+f"(c[1]), "+f"(c[2]), "+f"(c[3])
        : "r"(a[0]), "r"(a[1]), "r"(a[2]), "r"(a[3]), "r"(b0), "r"(b1));
}
__device__ __forceinline__ u32 pack_bf(__nv_bfloat16 a, __nv_bfloat16 b) {
    return (u32)__bfloat16_as_ushort(a) | ((u32)__bfloat16_as_ushort(b) << 16);
}
__device__ __forceinline__ void split4(float4 v, uint2& hi, uint2& lo) {
    __nv_bfloat16 h0 = __float2bfloat16(v.x), h1 = __float2bfloat16(v.y);
    __nv_bfloat16 h2 = __float2bfloat16(v.z), h3 = __float2bfloat16(v.w);
    __nv_bfloat16 l0 = __float2bfloat16(v.x - __bfloat162float(h0));
    __nv_bfloat16 l1 = __float2bfloat16(v.y - __bfloat162float(h1));
    __nv_bfloat16 l2 = __float2bfloat16(v.z - __bfloat162float(h2));
    __nv_bfloat16 l3 = __float2bfloat16(v.w - __bfloat162float(h3));
    hi = make_uint2(pack_bf(h0, h1), pack_bf(h2, h3));
    lo = make_uint2(pack_bf(l0, l1), pack_bf(l2, l3));
}

// ---------------------------------------------------------------------------
// Setup: weight splits + embedding combos + flag zeroing, one launch (80x256).
// ---------------------------------------------------------------------------
__global__ void conv_all_kernel(const float* __restrict__ Wenc,
                                const float* __restrict__ W1,
                                const float* __restrict__ W2,
                                const float* __restrict__ emb1,
                                const float* __restrict__ emb2) {
    int gid = blockIdx.x * blockDim.x + threadIdx.x;   // 0..20479

    // zero mask flags (12544 u32 covers MAXN bytes)
    if (gid < MAXN / 4) reinterpret_cast<u32*>(g_mflag)[gid] = 0u;

    // embedding combos: first 128 threads of block 0
    if (blockIdx.x == 0 && threadIdx.x < 128) {
        int i = threadIdx.x;
        #pragma unroll
        for (int t = 0; t < 6; t++)
            #pragma unroll
            for (int d = 0; d < 3; d++)
                g_embc[(t * 3 + d) * 128 + i] = emb1[t * 128 + i] + emb2[d * 128 + i];
    }

    // weight split (20480 float4 slots)
    int idx = gid;
    const float* src;
    int off;
    if (idx < 4096)       { src = Wenc; off = 0; }
    else if (idx < 12288) { src = W1;   off = 4096;  idx -= 4096; }
    else if (idx < 20480) { src = W2;   off = 12288; idx -= 12288; }
    else return;
    float4 v = reinterpret_cast<const float4*>(src)[idx];
    uint2 hi, lo;
    split4(v, hi, lo);
    reinterpret_cast<uint2*>(g_Wh)[off + idx] = hi;
    reinterpret_cast<uint2*>(g_Wl)[off + idx] = lo;
}

__global__ void flag_set_kernel(const int* __restrict__ mask, int Mm) {
    int i = blockIdx.x * blockDim.x + threadIdx.x;
    if (i < Mm) g_mflag[__ldg(mask + i)] = 1;
}

// ---------------------------------------------------------------------------
// Double-buffered HMMA bf16 split GEMM.
// C[M,Ntot] = f(A[M,K] @ B[Ntot,K]^T + bias),  D = Ah@Bh + Ah@Bl + Al@Bh.
// CTA 128x128, 256 thr (8 warps 2x4), K chunks of 64, 2-stage smem pipeline.
// MASKF: rows flagged in g_mflag write C=0 and C2=addvec (mask fold).
// ---------------------------------------------------------------------------
constexpr int RS   = 144;                 // smem row stride bytes (64 bf16 + 8 pad)
constexpr int TB   = 128 * RS;            // 18432 per tile buffer
constexpr int OAH = 0, OAL = TB, OBH = 2 * TB, OBL = 3 * TB;
constexpr int STG  = 4 * TB;              // 73728 per stage
constexpr int SMEMSZ = 2 * STG;           // 147456

template <int NC, bool ASPLIT, bool PRELU, bool RELU, bool BIAS, bool DUAL,
          bool WRITEC, bool TOUT, bool MASKF>
__global__ void __launch_bounds__(256)
mma_gemm(const float* __restrict__ A,
         const __nv_bfloat16* __restrict__ Asph, const __nv_bfloat16* __restrict__ Aspl,
         const __nv_bfloat16* __restrict__ Bh, const __nv_bfloat16* __restrict__ Bl,
         const float* __restrict__ bias, const float* __restrict__ prelu_pa,
         float* __restrict__ C, float* __restrict__ C2,
         const float* __restrict__ addvec,
         __nv_bfloat16* __restrict__ Th, __nv_bfloat16* __restrict__ Tl,
         int M, int Ntot) {
    extern __shared__ __align__(16) char smem[];
    const u32 s0 = smem_u32(smem);

    const int tid = threadIdx.x;
    const int wid = tid >> 5, lid = tid & 31;
    const int wm = wid >> 2;              // 0..1
    const int wn = wid & 3;               // 0..3
    const int rowbase = blockIdx.x * 128;
    const int colbase = blockIdx.y * 128;
    const int K = NC * 64;

    const float pa = PRELU ? *prelu_pa : 0.f;

    float acc[4][4][4];
    #pragma unroll
    for (int i = 0; i < 4; i++)
        #pragma unroll
        for (int j = 0; j < 4; j++)
            #pragma unroll
            for (int q = 0; q < 4; q++) acc[i][j][q] = 0.f;

    float4 av[4][2];

    auto ldgA = [&](int c) {
        #pragma unroll
        for (int i = 0; i < 4; i++) {
            int p = i * 256 + tid;
            int row = p >> 3, cp = p & 7;
            int grow = rowbase + row;
            if (grow < M) {
                const float4* s = reinterpret_cast<const float4*>(
                    A + (size_t)grow * K + c * 64 + cp * 8);
                av[i][0] = s[0]; av[i][1] = s[1];
            } else {
                av[i][0] = make_float4(0.f, 0.f, 0.f, 0.f);
                av[i][1] = make_float4(0.f, 0.f, 0.f, 0.f);
            }
        }
    };
    auto splitSTS = [&](u32 sb) {
        #pragma unroll
        for (int i = 0; i < 4; i++) {
            int p = i * 256 + tid;
            int row = p >> 3, cp = p & 7;
            float4 v0 = av[i][0], v1 = av[i][1];
            if (PRELU) {
                v0.x = v0.x > 0.f ? v0.x : pa * v0.x;
                v0.y = v0.y > 0.f ? v0.y : pa * v0.y;
                v0.z = v0.z > 0.f ? v0.z : pa * v0.z;
                v0.w = v0.w > 0.f ? v0.w : pa * v0.w;
                v1.x = v1.x > 0.f ? v1.x : pa * v1.x;
                v1.y = v1.y > 0.f ? v1.y : pa * v1.y;
                v1.z = v1.z > 0.f ? v1.z : pa * v1.z;
                v1.w = v1.w > 0.f ? v1.w : pa * v1.w;
            }
            uint2 h0, l0, h1, l1;
            split4(v0, h0, l0);
            split4(v1, h1, l1);
            *reinterpret_cast<uint4*>(smem + (sb - s0) + OAH + row * RS + cp * 16) =
                make_uint4(h0.x, h0.y, h1.x, h1.y);
            *reinterpret_cast<uint4*>(smem + (sb - s0) + OAL + row * RS + cp * 16) =
                make_uint4(l0.x, l0.y, l1.x, l1.y);
        }
    };
    auto cpB = [&](int c, u32 sb) {
        #pragma unroll
        for (int i = 0; i < 4; i++) {
            int j = i * 256 + tid;
            int row = j >> 3, c16 = j & 7;
            size_t go = (size_t)(colbase + row) * K + c * 64 + c16 * 8;
            cpa16(sb + OBH + row * RS + c16 * 16, Bh + go);
            cpa16(sb + OBL + row * RS + c16 * 16, Bl + go);
        }
    };
    auto cpA = [&](int c, u32 sb) {
        #pragma unroll
        for (int i = 0; i < 4; i++) {
            int j = i * 256 + tid;
            int row = j >> 3, c16 = j & 7;
            size_t go = (size_t)(rowbase + row) * K + c * 64 + c16 * 8;
            cpa16(sb + OAH + row * RS + c16 * 16, Asph + go);
            cpa16(sb + OAL + row * RS + c16 * 16, Aspl + go);
        }
    };
    auto compute = [&](u32 sb) {
        #pragma unroll
        for (int k = 0; k < 4; k++) {
            u32 bh[2][4], bl[2][4];
            #pragma unroll
            for (int nj = 0; nj < 2; nj++) {
                int row = wn * 32 + nj * 16 + (lid & 7) + ((lid >> 4) << 3);
                int colb = k * 32 + ((lid >> 3) & 1) * 16;
                ldsm4(bh[nj][0], bh[nj][1], bh[nj][2], bh[nj][3],
                      sb + OBH + row * RS + colb);
                ldsm4(bl[nj][0], bl[nj][1], bl[nj][2], bl[nj][3],
                      sb + OBL + row * RS + colb);
            }
            #pragma unroll
            for (int mi = 0; mi < 4; mi++) {
                int arow = wm * 64 + mi * 16 + (lid & 15);
                int acolb = k * 32 + ((lid >> 4) << 4);
                u32 ah[4], al[4];
                ldsm4(ah[0], ah[1], ah[2], ah[3], sb + OAH + arow * RS + acolb);
                ldsm4(al[0], al[1], al[2], al[3], sb + OAL + arow * RS + acolb);
                #pragma unroll
                for (int n8 = 0; n8 < 4; n8++) {
                    int nj = n8 >> 1, p = (n8 & 1) * 2;
                    mma16816(acc[mi][n8], ah, bh[nj][p], bh[nj][p + 1]);
                    mma16816(acc[mi][n8], ah, bl[nj][p], bl[nj][p + 1]);
                    mma16816(acc[mi][n8], al, bh[nj][p], bh[nj][p + 1]);
                }
            }
        }
    };

    // ---- prologue ----
    if (ASPLIT) ldgA(0); else cpA(0, s0);
    cpB(0, s0);
    cpa_commit();
    if (ASPLIT) splitSTS(s0);
    cpa_wait0();
    __syncthreads();

    // ---- pipelined mainloop ----
    #pragma unroll
    for (int c = 0; c < NC; c++) {
        u32 sb = s0 + (c & 1) * STG;
        u32 sn = s0 + ((c + 1) & 1) * STG;
        if (c + 1 < NC) {
            if (ASPLIT) ldgA(c + 1); else cpA(c + 1, sn);
            cpB(c + 1, sn);
            cpa_commit();
        }
        compute(sb);
        if (c + 1 < NC) {
            if (ASPLIT) splitSTS(sn);
            cpa_wait0();
            __syncthreads();
        }
    }

    // ---- epilogue ----
    const int g = lid >> 2, t = lid & 3;
    #pragma unroll
    for (int mi = 0; mi < 4; mi++) {
        int gr0 = rowbase + wm * 64 + mi * 16 + g;
        int gr1 = gr0 + 8;
        bool m0 = false, m1 = false;
        if (MASKF) {
            if (gr0 < M) m0 = (g_mflag[gr0] != 0);
            if (gr1 < M) m1 = (g_mflag[gr1] != 0);
        }
        #pragma unroll
        for (int n8 = 0; n8 < 4; n8++) {
            int gc  = colbase + wn * 32 + n8 * 8 + 2 * t;
            float c0 = acc[mi][n8][0], c1 = acc[mi][n8][1];
            float c2 = acc[mi][n8][2], c3 = acc[mi][n8][3];
            if (BIAS) {
                float bb0 = __ldg(bias + gc), bb1 = __ldg(bias + gc + 1);
                c0 += bb0; c1 += bb1; c2 += bb0; c3 += bb1;
            }
            if (RELU) {
                c0 = fmaxf(c0, 0.f); c1 = fmaxf(c1, 0.f);
                c2 = fmaxf(c2, 0.f); c3 = fmaxf(c3, 0.f);
            }
            if (MASKF) {
                if (m0) { c0 = 0.f; c1 = 0.f; }
                if (m1) { c2 = 0.f; c3 = 0.f; }
            }
            if (WRITEC) {
                float av0 = 0.f, av1 = 0.f;
                if (DUAL) { av0 = __ldg(addvec + gc); av1 = __ldg(addvec + gc + 1); }
                if (gr0 < M) {
                    *reinterpret_cast<float2*>(C + (size_t)gr0 * Ntot + gc) =
                        make_float2(c0, c1);
                    if (DUAL)
                        *reinterpret_cast<float2*>(C2 + (size_t)gr0 * Ntot + gc) =
                            make_float2(c0 + av0, c1 + av1);
                }
                if (gr1 < M) {
                    *reinterpret_cast<float2*>(C + (size_t)gr1 * Ntot + gc) =
                        make_float2(c2, c3);
                    if (DUAL)
                        *reinterpret_cast<float2*>(C2 + (size_t)gr1 * Ntot + gc) =
                            make_float2(c2 + av0, c3 + av1);
                }
            }
            if (TOUT) {
                if (gr0 < M) {
                    __nv_bfloat16 h0 = __float2bfloat16(c0), h1 = __float2bfloat16(c1);
                    __nv_bfloat16 l0 = __float2bfloat16(c0 - __bfloat162float(h0));
                    __nv_bfloat16 l1 = __float2bfloat16(c1 - __bfloat162float(h1));
                    *reinterpret_cast<u32*>(Th + (size_t)gr0 * Ntot + gc) = pack_bf(h0, h1);
                    *reinterpret_cast<u32*>(Tl + (size_t)gr0 * Ntot + gc) = pack_bf(l0, l1);
                }
                if (gr1 < M) {
                    __nv_bfloat16 h2 = __float2bfloat16(c2), h3 = __float2bfloat16(c3);
                    __nv_bfloat16 l2 = __float2bfloat16(c2 - __bfloat162float(h2));
                    __nv_bfloat16 l3 = __float2bfloat16(c3 - __bfloat162float(h3));
                    *reinterpret_cast<u32*>(Th + (size_t)gr1 * Ntot + gc) = pack_bf(h2, h3);
                    *reinterpret_cast<u32*>(Tl + (size_t)gr1 * Ntot + gc) = pack_bf(l2, l3);
                }
            }
        }
    }
}

// ---------------------------------------------------------------------------
// Edge scatter: 4 consecutive edges per warp; indices loaded up-front, then
// 4 independent gathers + 4 red.global.add.v4 (MLP=4 per warp).
// ---------------------------------------------------------------------------
__global__ void scatter_kernel(const int* __restrict__ ei,
                               const int* __restrict__ ea, int E) {
    int gw = (blockIdx.x * blockDim.x + threadIdx.x) >> 5;
    int lane = threadIdx.x & 31;
    int e0 = gw * 4;
    if (e0 >= E) return;
    int n = E - e0;
    if (n > 4) n = 4;

    const float4* hb = reinterpret_cast<const float4*>(g_h);
    const float4* eb = reinterpret_cast<const float4*>(g_embc);

    int src[4], dst[4], cb[4];
    #pragma unroll
    for (int i = 0; i < 4; i++) {
        int e = e0 + (i < n ? i : 0);
        src[i] = __ldg(ei + e);
        dst[i] = __ldg(ei + E + e);
        int2 aa = *reinterpret_cast<const int2*>(ea + 2 * e);
        cb[i] = aa.x * 3 + aa.y;
    }

    float4 hv[4], ev[4];
    #pragma unroll
    for (int i = 0; i < 4; i++) {
        hv[i] = hb[(size_t)src[i] * 32 + lane];
        ev[i] = eb[cb[i] * 32 + lane];
    }

    #pragma unroll
    for (int i = 0; i < 4; i++) {
        if (i < n) {
            float4 m = make_float4(hv[i].x + ev[i].x, hv[i].y + ev[i].y,
                                   hv[i].z + ev[i].z, hv[i].w + ev[i].w);
            float* p = g_aggr + (size_t)dst[i] * 128 + lane * 4;
            asm volatile("red.global.add.v4.f32 [%0], {%1, %2, %3, %4};"
                         :: "l"(p), "f"(m.x), "f"(m.y), "f"(m.z), "f"(m.w)
                         : "memory");
        }
    }
}

// ---------------------------------------------------------------------------
// Host launch
// ---------------------------------------------------------------------------
extern "C" void kernel_launch(void* const* d_in, const int* in_sizes, int n_in,
                              void* d_out, int out_size) {
    const float* x    = (const float*)d_in[0];
    const int*   ei   = (const int*)d_in[1];
    const int*   ea   = (const int*)d_in[2];
    const int*   mask = (const int*)d_in[3];
    const float* pa   = (const float*)d_in[4];
    const float* Wenc = (const float*)d_in[5];
    const float* W1   = (const float*)d_in[6];
    const float* b1   = (const float*)d_in[7];
    const float* W2   = (const float*)d_in[8];
    const float* b2   = (const float*)d_in[9];
    const float* emb1 = (const float*)d_in[10];
    const float* emb2 = (const float*)d_in[11];

    int N  = in_sizes[0] / 128;
    int E  = in_sizes[1] / 2;
    int Mm = in_sizes[3];
    float* out = (float*)d_out;

    float *h, *aggr, *embc;
    __nv_bfloat16 *wh, *wl, *th, *tl;
    cudaGetSymbolAddress((void**)&h,    g_h);
    cudaGetSymbolAddress((void**)&aggr, g_aggr);
    cudaGetSymbolAddress((void**)&embc, g_embc);
    cudaGetSymbolAddress((void**)&wh,   g_Wh);
    cudaGetSymbolAddress((void**)&wl,   g_Wl);
    cudaGetSymbolAddress((void**)&th,   g_th);
    cudaGetSymbolAddress((void**)&tl,   g_tl);

    // G1: fp32-A, PReLU, DUAL aggr init, fp32 out, mask fold
    auto k1 = mma_gemm<2, true,  true,  false, false, true,  true,  false, true>;
    // G2: fp32-A, RELU+bias, split-bf16 out only
    auto k2 = mma_gemm<2, true,  false, true,  true,  false, false, true,  false>;
    // G3: bf16-A (cp.async), bias, fp32 out
    auto k3 = mma_gemm<4, false, false, false, true,  false, true,  false, false>;
    cudaFuncSetAttribute(k1, cudaFuncAttributeMaxDynamicSharedMemorySize, SMEMSZ);
    cudaFuncSetAttribute(k2, cudaFuncAttributeMaxDynamicSharedMemorySize, SMEMSZ);
    cudaFuncSetAttribute(k3, cudaFuncAttributeMaxDynamicSharedMemorySize, SMEMSZ);

    // 0) setup: weight splits + emb combos + flag zero, then flag set
    conv_all_kernel<<<80, 256>>>(Wenc, W1, W2, emb1, emb2);
    flag_set_kernel<<<(Mm + 255) / 256, 256>>>(mask, Mm);

    int gx = (N + 127) / 128;

    // 1) G1: h = PReLU(x) @ Wenc^T (masked rows -> 0) ; aggr = h + selfc
    k1<<<dim3(gx, 1), 256, SMEMSZ>>>(x, nullptr, nullptr, wh, wl, nullptr, pa,
                                     h, aggr, embc + 12 * 128, nullptr, nullptr,
                                     N, 128);

    // 2) edge scatter (atomic accumulate into aggr), 4 edges/warp
    int warps = (E + 3) / 4;
    int blocks = (warps * 32 + 255) / 256;
    scatter_kernel<<<blocks, 256>>>(ei, ea, E);

    // 3) G2: t = relu(aggr @ W1^T + b1) -> split bf16 th/tl
    k2<<<dim3(gx, 2), 256, SMEMSZ>>>(aggr, nullptr, nullptr, wh + 16384, wl + 16384,
                                     b1, nullptr, nullptr, nullptr, nullptr,
                                     th, tl, N, 256);

    // 4) G3: out = t @ W2^T + b2
    k3<<<dim3(gx, 1), 256, SMEMSZ>>>(nullptr, th, tl, wh + 49152, wl + 49152,
                                     b2, nullptr, out, nullptr, nullptr,
                                     nullptr, nullptr, N, 128);
}